// round 16
// baseline (speedup 1.0000x reference)
#include <cuda_runtime.h>
#include <cuda_fp16.h>
#include <cstdint>

// Problem constants
#define Bsz 2
#define Sq 8192
#define HQ 32
#define HKn 8
#define Dd 128
#define GHd 128
#define NBl 128
#define Gg 4
#define K1 512   // G*D

#define NT 256   // threads per CTA (8 warps); 2 CTAs co-resident per SM
#define MR 64    // M rows per CTA

// ---------------- device scratch (no allocs allowed) ----------------
__device__ __align__(16) __half g_wqT_hi[HKn * GHd * K1];   // [kh][n][k]
__device__ __align__(16) __half g_wqT_lo[HKn * GHd * K1];
__device__ __align__(16) __half g_kp_hi[Bsz * HKn * NBl * GHd]; // [b][kh][n][gh]
__device__ __align__(16) __half g_kp_lo[Bsz * HKn * NBl * GHd];

// ---------------- helpers ----------------
__device__ __forceinline__ void mma16816(float* c, const uint32_t* a, const uint32_t* b) {
    asm volatile(
        "mma.sync.aligned.m16n8k16.row.col.f32.f16.f16.f32 "
        "{%0,%1,%2,%3},{%4,%5,%6,%7},{%8,%9},{%0,%1,%2,%3};\n"
        : "+f"(c[0]), "+f"(c[1]), "+f"(c[2]), "+f"(c[3])
        : "r"(a[0]), "r"(a[1]), "r"(a[2]), "r"(a[3]), "r"(b[0]), "r"(b[1]));
}

__device__ __forceinline__ void ldsm4(uint32_t* r, uint32_t addr) {
    asm volatile("ldmatrix.sync.aligned.m8n8.x4.shared.b16 {%0,%1,%2,%3},[%4];"
                 : "=r"(r[0]), "=r"(r[1]), "=r"(r[2]), "=r"(r[3]) : "r"(addr));
}

__device__ __forceinline__ void cp16(uint32_t dst, const void* src) {
    asm volatile("cp.async.cg.shared.global [%0], [%1], 16;" :: "r"(dst), "l"(src));
}
__device__ __forceinline__ void cp_commit() { asm volatile("cp.async.commit_group;" ::: "memory"); }
__device__ __forceinline__ void cp_wait_all() { asm volatile("cp.async.wait_group 0;" ::: "memory"); }

__device__ __forceinline__ uint32_t h2u(__half2 h) { return *(uint32_t*)&h; }

__device__ __forceinline__ void split_f32(float v, __half& hi, __half& lo) {
    hi = __float2half_rn(v);
    lo = __float2half_rn(v - __half2float(hi));
}

// ---------------- merged prep kernel: wq split/transpose + K path ----------------
// Blocks [0,512): wq tile transpose+split.
// Blocks [512,2560): kpath, one (b,h,n) per block, vectorized float4 pooling.
__global__ void prep_all(const float* __restrict__ wq, const float* __restrict__ k,
                         const float* __restrict__ cosk, const float* __restrict__ sink,
                         const float* __restrict__ wk) {
    __shared__ float tile[32][33];
    __shared__ float4 ssum[8][32];
    __shared__ float4 smax[8][32];
    __shared__ float kc[2 * Dd];
    __shared__ float s_mv[2][Dd];
    __shared__ float kps[GHd];

    if (blockIdx.x < 512) {
        // ---- wq: [kh][k=512][n=128] -> split hi/lo, transposed [kh][n][k] ----
        int bx = blockIdx.x;
        int kx = bx & 15;
        int ny = (bx >> 4) & 3;
        int kh = bx >> 6;
        int k0 = kx * 32;
        int n0 = ny * 32;
        int tx = threadIdx.x & 31;
        int ty4 = threadIdx.x >> 5;
        const float* src = wq + ((size_t)kh * K1 + k0) * GHd + n0;
#pragma unroll
        for (int j = 0; j < 4; j++) {
            int kk = ty4 * 4 + j;
            tile[kk][tx] = src[(size_t)kk * GHd + tx];
        }
        __syncthreads();
#pragma unroll
        for (int j = 0; j < 4; j++) {
            int nn = ty4 * 4 + j;
            float v = tile[tx][nn];
            __half hi, lo;
            split_f32(v, hi, lo);
            size_t o = ((size_t)kh * GHd + n0 + nn) * K1 + k0 + tx;
            g_wqT_hi[o] = hi;
            g_wqT_lo[o] = lo;
        }
    } else {
        // ---- kpath: vectorized pool (mean+max) + matvec + rope ----
        int id   = blockIdx.x - 512;       // 0..2047
        int n    = id & 127;
        int h    = (id >> 7) & 7;
        int b    = id >> 10;

        int rg = threadIdx.x >> 5;         // 0..7 row group
        int cc = threadIdx.x & 31;         // float4 column (d = cc*4 .. cc*4+3)

        // each thread pools rows {rg, rg+8, .., rg+56} at columns cc*4..cc*4+3
        const float4* kbase = (const float4*)(k +
            (((size_t)b * Sq + (size_t)n * 64 + rg) * HKn + h) * Dd) + cc;
        const size_t rstride4 = (size_t)8 * HKn * Dd / 4;   // 8 rows in float4 units
        float4 sum = make_float4(0.f, 0.f, 0.f, 0.f);
        float4 mx  = make_float4(-3.4e38f, -3.4e38f, -3.4e38f, -3.4e38f);
#pragma unroll
        for (int it = 0; it < 8; it++) {
            float4 v = kbase[it * rstride4];
            sum.x += v.x; sum.y += v.y; sum.z += v.z; sum.w += v.w;
            mx.x = fmaxf(mx.x, v.x); mx.y = fmaxf(mx.y, v.y);
            mx.z = fmaxf(mx.z, v.z); mx.w = fmaxf(mx.w, v.w);
        }
        ssum[rg][cc] = sum;
        smax[rg][cc] = mx;
        __syncthreads();

        // tree reduce over row groups (8 -> 1)
#pragma unroll
        for (int s = 4; s >= 1; s >>= 1) {
            if (rg < s) {
                float4 a = ssum[rg][cc], bb = ssum[rg + s][cc];
                a.x += bb.x; a.y += bb.y; a.z += bb.z; a.w += bb.w;
                ssum[rg][cc] = a;
                float4 ma = smax[rg][cc], mb = smax[rg + s][cc];
                ma.x = fmaxf(ma.x, mb.x); ma.y = fmaxf(ma.y, mb.y);
                ma.z = fmaxf(ma.z, mb.z); ma.w = fmaxf(ma.w, mb.w);
                smax[rg][cc] = ma;
            }
            __syncthreads();
        }

        // kc[0..127]=mean, kc[128..255]=max
        {
            int tt = threadIdx.x;
            int d4 = (tt & 127) >> 2;
            int j  = tt & 3;
            if (tt < Dd) {
                const float* p = (const float*)&ssum[0][d4];
                kc[tt] = p[j] * (1.0f / 64.0f);
            } else {
                const float* p = (const float*)&smax[0][d4];
                kc[tt] = p[j];
            }
        }
        __syncthreads();

        // matvec: (d, half) covers i in [half*128, half*128+128)
        int d    = threadIdx.x & 127;
        int half = threadIdx.x >> 7;
        float acc = 0.f;
        const float* wkb = wk + (size_t)h * (2 * Dd) * GHd + (size_t)(half * Dd) * GHd + d;
#pragma unroll 8
        for (int i = 0; i < Dd; i++) acc += kc[half * Dd + i] * wkb[(size_t)i * GHd];
        s_mv[half][d] = acc;
        __syncthreads();

        if (half == 0) {
            kps[d] = s_mv[0][d] + s_mv[1][d];
        }
        __syncthreads();
        if (half == 0) {
            float full = kps[d];
            float rot = (d < 64) ? -kps[d + 64] : kps[d - 64];
            size_t ci = ((size_t)b * NBl + n) * GHd + d;
            float o = full * cosk[ci] + rot * sink[ci];
            __half hi, lo;
            split_f32(o, hi, lo);
            size_t oi = (((size_t)b * HKn + h) * NBl + n) * GHd + d;
            g_kp_hi[oi] = hi;
            g_kp_lo[oi] = lo;
        }
    }
}

// ---------------- fused kernel smem geometry (64-row CTA, R14 winner) ----------------
#define LDA 72      // halves per smem row (phase1): 144B = 9*16B
#define LDQ 129     // floats (logits staging)
#define LD2 136     // halves (phase2/3 tiles): 272B
#define A_SZ 9216            // 64*LDA*2
#define W_SZ 18432           // 128*LDA*2
#define BUFB 55296           // Ah(9216) Al(9216) Wh(18432) Wl(18432)
#define AS2_HALF 17408       // 64*LD2*2
#define AS2_OFF 0            // overlays phase-1 buffer 0
#define BS2_OFF 34816        // kp tiles (loaded after phase 1)
#define BS2_HALF 34816       // 128*LD2*2
#define SMEM_TOTAL 110592    // 2 CTAs/SM -> 216 KB

// Warp-tile GEMM (phase 1): 8 warps, warp owns 32(m) x 32(n),
// n-rows {wn*16..+15} U {64+wn*16..+15}. Term-major, all f32 accum.
template <int LD, int KS>
__device__ __forceinline__ void gemm_tile(uint32_t Ah, uint32_t Al, uint32_t Bh, uint32_t Bl,
                                          float acc[2][4][4]) {
#pragma unroll
    for (int kk = 0; kk < KS; kk++) {
        const int ks = kk * 16;
        uint32_t ah[2][4], al[2][4], bh[4][2], bl[4][2];
#pragma unroll
        for (int mi = 0; mi < 2; mi++) {
            ldsm4(ah[mi], Ah + (mi * 16 * LD + ks) * 2);
            ldsm4(al[mi], Al + (mi * 16 * LD + ks) * 2);
        }
#pragma unroll
        for (int p = 0; p < 2; p++) {
            const int prow = p * 64;
            uint32_t r[4];
            ldsm4(r, Bh + (prow * LD + ks) * 2);
            bh[2 * p][0] = r[0]; bh[2 * p][1] = r[1];
            bh[2 * p + 1][0] = r[2]; bh[2 * p + 1][1] = r[3];
            ldsm4(r, Bl + (prow * LD + ks) * 2);
            bl[2 * p][0] = r[0]; bl[2 * p][1] = r[1];
            bl[2 * p + 1][0] = r[2]; bl[2 * p + 1][1] = r[3];
        }
#pragma unroll
        for (int mi = 0; mi < 2; mi++)
#pragma unroll
            for (int nj = 0; nj < 4; nj++)
                mma16816(acc[mi][nj], ah[mi], bh[nj]);
#pragma unroll
        for (int mi = 0; mi < 2; mi++)
#pragma unroll
            for (int nj = 0; nj < 4; nj++)
                mma16816(acc[mi][nj], ah[mi], bl[nj]);
#pragma unroll
        for (int mi = 0; mi < 2; mi++)
#pragma unroll
            for (int nj = 0; nj < 4; nj++)
                mma16816(acc[mi][nj], al[mi], bh[nj]);
    }
}

// Phase-3 GEMM with causal-mask group skipping. needLo/needHi are warp-uniform.
template <int LD, int KS>
__device__ __forceinline__ void gemm_tile_attn(uint32_t Ah, uint32_t Al, uint32_t Bh, uint32_t Bl,
                                               float acc[2][4][4], bool needLo, bool needHi) {
    if (!(needLo || needHi)) return;
#pragma unroll
    for (int kk = 0; kk < KS; kk++) {
        const int ks = kk * 16;
        uint32_t ah[2][4], al[2][4], bh[4][2], bl[4][2];
#pragma unroll
        for (int mi = 0; mi < 2; mi++) {
            ldsm4(ah[mi], Ah + (mi * 16 * LD + ks) * 2);
            ldsm4(al[mi], Al + (mi * 16 * LD + ks) * 2);
        }
        if (needLo) {
            uint32_t r[4];
            ldsm4(r, Bh + ks * 2);
            bh[0][0] = r[0]; bh[0][1] = r[1]; bh[1][0] = r[2]; bh[1][1] = r[3];
            ldsm4(r, Bl + ks * 2);
            bl[0][0] = r[0]; bl[0][1] = r[1]; bl[1][0] = r[2]; bl[1][1] = r[3];
        }
        if (needHi) {
            uint32_t r[4];
            ldsm4(r, Bh + (64 * LD + ks) * 2);
            bh[2][0] = r[0]; bh[2][1] = r[1]; bh[3][0] = r[2]; bh[3][1] = r[3];
            ldsm4(r, Bl + (64 * LD + ks) * 2);
            bl[2][0] = r[0]; bl[2][1] = r[1]; bl[3][0] = r[2]; bl[3][1] = r[3];
        }
        if (needLo) {
#pragma unroll
            for (int mi = 0; mi < 2; mi++)
#pragma unroll
                for (int nj = 0; nj < 2; nj++) {
                    mma16816(acc[mi][nj], ah[mi], bh[nj]);
                    mma16816(acc[mi][nj], ah[mi], bl[nj]);
                    mma16816(acc[mi][nj], al[mi], bh[nj]);
                }
        }
        if (needHi) {
#pragma unroll
            for (int mi = 0; mi < 2; mi++)
#pragma unroll
                for (int nj = 2; nj < 4; nj++) {
                    mma16816(acc[mi][nj], ah[mi], bh[nj]);
                    mma16816(acc[mi][nj], ah[mi], bl[nj]);
                    mma16816(acc[mi][nj], al[mi], bh[nj]);
                }
        }
    }
}

__global__ void __launch_bounds__(NT, 2)
fused_attn(const float* __restrict__ q, const float* __restrict__ cosq,
           const float* __restrict__ sinq, float* __restrict__ out) {
    extern __shared__ char sm[];
    const uint32_t su = (uint32_t)__cvta_generic_to_shared(sm);

    const int t    = threadIdx.x;
    const int lane = t & 31;
    const int w    = t >> 5;       // 0..7
    const int wm   = w >> 2;       // 0..1
    const int wn   = w & 3;        // 0..3
    const int gid  = lane >> 2;
    const int tig  = lane & 3;

    // reversed s-tile mapping: last-launched CTAs get the cheapest (low-nv) tiles
    const int rbx = 127 - (int)blockIdx.x;
    const int s0 = rbx * MR;
    const int kh = blockIdx.y;
    const int b  = blockIdx.z;

    // causal block mask: valid columns for this CTA = 0 .. nv-1
    const int nv = rbx + 1;
    const bool needLo = nv > wn * 16;
    const bool needHi = nv > 64 + wn * 16;

    // ldmatrix lane offsets (bytes)
    const uint32_t aoff1 = (uint32_t)(((wm * 32 + (lane & 15)) * LDA + ((lane >> 4) << 3)) * 2);
    const uint32_t boff1 = (uint32_t)(((wn * 16 + (lane & 7) + ((lane >> 4) << 3)) * LDA +
                                       (((lane >> 3) & 1) << 3)) * 2);
    const uint32_t aoff2 = (uint32_t)(((wm * 32 + (lane & 15)) * LD2 + ((lane >> 4) << 3)) * 2);
    const uint32_t boff2 = (uint32_t)(((wn * 16 + (lane & 7) + ((lane >> 4) << 3)) * LD2 +
                                       (((lane >> 3) & 1) << 3)) * 2);

    float acc[2][4][4];
#pragma unroll
    for (int mi = 0; mi < 2; mi++)
#pragma unroll
        for (int nj = 0; nj < 4; nj++)
#pragma unroll
            for (int c = 0; c < 4; c++) acc[mi][nj][c] = 0.f;

    const float* qbase = q + ((size_t)b * Sq + s0) * (HQ * Dd) + (size_t)kh * (Gg * Dd);
    const __half* wqh = g_wqT_hi + (size_t)kh * GHd * K1;
    const __half* wql = g_wqT_lo + (size_t)kh * GHd * K1;

    // per-thread load indices (phase 1, 64-wide chunks, 256 threads)
    int qrow[4], wrow[4];
#pragma unroll
    for (int i = 0; i < 4; i++) qrow[i] = (t + NT * i) >> 4;   // 16 float4 per A row (64 rows)
    const int qc4 = (t & 15) << 2;
#pragma unroll
    for (int i = 0; i < 4; i++) wrow[i] = (t + NT * i) >> 3;   // 8 cp16 per W row (128 rows)
    const int wc8 = (t & 7) << 3;

    float4 qv[4];

    // ---- prologue: chunk 0 (weights cp.async FIRST, then the q LDG chain) ----
#pragma unroll
    for (int i = 0; i < 4; i++) {
        uint32_t d = su + 2 * A_SZ + (uint32_t)((wrow[i] * LDA + wc8) * 2);
        cp16(d, wqh + (size_t)wrow[i] * K1 + wc8);
        cp16(d + W_SZ, wql + (size_t)wrow[i] * K1 + wc8);
    }
    cp_commit();
#pragma unroll
    for (int i = 0; i < 4; i++)
        qv[i] = *(const float4*)(qbase + (size_t)qrow[i] * (HQ * Dd) + qc4);
    {
        char* buf = sm;
        __half* Ah = (__half*)buf;
        __half* Al = (__half*)(buf + A_SZ);
#pragma unroll
        for (int i = 0; i < 4; i++) {
            __half2 h01 = __floats2half2_rn(qv[i].x, qv[i].y);
            __half2 h23 = __floats2half2_rn(qv[i].z, qv[i].w);
            __half2 l01 = __floats2half2_rn(qv[i].x - __low2float(h01), qv[i].y - __high2float(h01));
            __half2 l23 = __floats2half2_rn(qv[i].z - __low2float(h23), qv[i].w - __high2float(h23));
            *(uint2*)(Ah + qrow[i] * LDA + qc4) = make_uint2(h2u(h01), h2u(h23));
            *(uint2*)(Al + qrow[i] * LDA + qc4) = make_uint2(h2u(l01), h2u(l23));
        }
    }

    // ===== Phase 1: Q projection, K=512 in 8 chunks of 64, double-buffered =====
    for (int c = 0; c < 8; c++) {
        cp_wait_all();
        __syncthreads();
        const int kc_next = (c + 1) * 64;
        if (c < 7) {
            uint32_t nb = su + ((c + 1) & 1) * BUFB;
#pragma unroll
            for (int i = 0; i < 4; i++) {
                uint32_t d = nb + 2 * A_SZ + (uint32_t)((wrow[i] * LDA + wc8) * 2);
                cp16(d, wqh + (size_t)wrow[i] * K1 + kc_next + wc8);
                cp16(d + W_SZ, wql + (size_t)wrow[i] * K1 + kc_next + wc8);
            }
            cp_commit();
#pragma unroll
            for (int i = 0; i < 4; i++)
                qv[i] = *(const float4*)(qbase + (size_t)qrow[i] * (HQ * Dd) + kc_next + qc4);
        }
        {
            const uint32_t bb = su + (c & 1) * BUFB;
            gemm_tile<LDA, 4>(bb + aoff1, bb + A_SZ + aoff1,
                              bb + 2 * A_SZ + boff1, bb + 2 * A_SZ + W_SZ + boff1, acc);
        }
        if (c < 7) {
            char* buf = sm + ((c + 1) & 1) * BUFB;
            __half* Ah = (__half*)buf;
            __half* Al = (__half*)(buf + A_SZ);
#pragma unroll
            for (int i = 0; i < 4; i++) {
                __half2 h01 = __floats2half2_rn(qv[i].x, qv[i].y);
                __half2 h23 = __floats2half2_rn(qv[i].z, qv[i].w);
                __half2 l01 = __floats2half2_rn(qv[i].x - __low2float(h01), qv[i].y - __high2float(h01));
                __half2 l23 = __floats2half2_rn(qv[i].z - __low2float(h23), qv[i].w - __high2float(h23));
                *(uint2*)(Ah + qrow[i] * LDA + qc4) = make_uint2(h2u(h01), h2u(h23));
                *(uint2*)(Al + qrow[i] * LDA + qc4) = make_uint2(h2u(l01), h2u(l23));
            }
        }
    }
    __syncthreads();   // phase-1 buffers dead

    // ===== issue kp tile loads, only rows < nv (rounded to ldmatrix group) =====
    {
        const int nvp = (nv + 15) & ~15;
        const __half* kph = g_kp_hi + ((size_t)b * HKn + kh) * NBl * GHd;
        const __half* kpl = g_kp_lo + ((size_t)b * HKn + kh) * NBl * GHd;
#pragma unroll
        for (int i = 0; i < 8; i++) {
            int id = t + NT * i;
            int n  = id >> 4;
            int c8 = (id & 15) << 3;
            if (n < nvp) {
                uint32_t d = su + BS2_OFF + (uint32_t)((n * LD2 + c8) * 2);
                cp16(d, kph + (size_t)n * GHd + c8);
                cp16(d + BS2_HALF, kpl + (size_t)n * GHd + c8);
            }
        }
        cp_commit();
    }

    // ===== Phase 2: register RoPE + split -> As2 =====
    {
        __half* As2_hi = (__half*)(sm + AS2_OFF);
        __half* As2_lo = (__half*)(sm + AS2_OFF + AS2_HALF);
        const size_t rowbase = (size_t)b * Sq + s0;
#pragma unroll
        for (int j = 0; j < 2; j++) {
            const int cl = wn * 16 + j * 8 + tig * 2;
            const int ch = cl + 64;
#pragma unroll
            for (int mi = 0; mi < 2; mi++)
#pragma unroll
                for (int h = 0; h < 2; h++) {
                    int row = wm * 32 + mi * 16 + h * 8 + gid;
                    const float* crow = cosq + (rowbase + row) * GHd;
                    const float* srow = sinq + (rowbase + row) * GHd;
                    float2 c_l = *(const float2*)(crow + cl);
                    float2 c_h = *(const float2*)(crow + ch);
                    float2 s_l = *(const float2*)(srow + cl);
                    float2 s_h = *(const float2*)(srow + ch);
                    float vl0 = acc[mi][j][2 * h],     vl1 = acc[mi][j][2 * h + 1];
                    float vh0 = acc[mi][j + 2][2 * h], vh1 = acc[mi][j + 2][2 * h + 1];
                    float ol0 = vl0 * c_l.x - vh0 * s_l.x;
                    float ol1 = vl1 * c_l.y - vh1 * s_l.y;
                    float oh0 = vh0 * c_h.x + vl0 * s_h.x;
                    float oh1 = vh1 * c_h.y + vl1 * s_h.y;
                    __half2 hl = __floats2half2_rn(ol0, ol1);
                    __half2 hh = __floats2half2_rn(oh0, oh1);
                    __half2 ll = __floats2half2_rn(ol0 - __low2float(hl), ol1 - __high2float(hl));
                    __half2 lh = __floats2half2_rn(oh0 - __low2float(hh), oh1 - __high2float(hh));
                    *(uint32_t*)(As2_hi + row * LD2 + cl) = h2u(hl);
                    *(uint32_t*)(As2_hi + row * LD2 + ch) = h2u(hh);
                    *(uint32_t*)(As2_lo + row * LD2 + cl) = h2u(ll);
                    *(uint32_t*)(As2_lo + row * LD2 + ch) = h2u(lh);
                }
        }
    }
    cp_wait_all();
    __syncthreads();   // As2 + Bs2 ready

    // ===== Phase 3: attn split-GEMM K=128, masked n-groups skipped =====
#pragma unroll
    for (int mi = 0; mi < 2; mi++)
#pragma unroll
        for (int nj = 0; nj < 4; nj++)
#pragma unroll
            for (int c = 0; c < 4; c++) acc[mi][nj][c] = 0.f;

    gemm_tile_attn<LD2, 8>(su + AS2_OFF + aoff2, su + AS2_OFF + AS2_HALF + aoff2,
                           su + BS2_OFF + boff2, su + BS2_OFF + BS2_HALF + boff2,
                           acc, needLo, needHi);
    __syncthreads();   // As2 dead

    // ===== Phase 4: logits (remapped cols), masked softmax, store =====
    float* logits = (float*)sm;
    const float scale = 0.08838834764831845f;  // 1/sqrt(128)
#pragma unroll
    for (int mi = 0; mi < 2; mi++)
#pragma unroll
        for (int nj = 0; nj < 4; nj++) {
            const bool need = (nj < 2) ? needLo : needHi;
            if (need) {
                int r = wm * 32 + mi * 16 + gid;
                int col = wn * 16 + (nj & 1) * 8 + ((nj >> 1) << 6) + tig * 2;
                logits[r * LDQ + col]           = acc[mi][nj][0] * scale;
                logits[r * LDQ + col + 1]       = acc[mi][nj][1] * scale;
                logits[(r + 8) * LDQ + col]     = acc[mi][nj][2] * scale;
                logits[(r + 8) * LDQ + col + 1] = acc[mi][nj][3] * scale;
            }
        }
    __syncthreads();

    for (int rr = 0; rr < 8; rr++) {
        int row    = w * 8 + rr;
        int sabs   = s0 + row;
        int nvalid = (sabs >> 6) + 1;
        float v[4];
#pragma unroll
        for (int j = 0; j < 4; j++) {
            int c = lane + j * 32;
            v[j] = (c < nvalid) ? logits[row * LDQ + c] : -1e30f;
        }
        float m = fmaxf(fmaxf(v[0], v[1]), fmaxf(v[2], v[3]));
#pragma unroll
        for (int o = 16; o; o >>= 1) m = fmaxf(m, __shfl_xor_sync(0xffffffffu, m, o));
        float e[4];
        float se = 0.f;
#pragma unroll
        for (int j = 0; j < 4; j++) { e[j] = __expf(v[j] - m); se += e[j]; }
#pragma unroll
        for (int o = 16; o; o >>= 1) se += __shfl_xor_sync(0xffffffffu, se, o);
        float inv = 1.0f / se;
        float* orow = out + (((size_t)b * HKn + kh) * Sq + sabs) * NBl;
#pragma unroll
        for (int j = 0; j < 4; j++) {
            int c = lane + j * 32;
            orow[c] = (c < nvalid) ? e[j] * inv : 0.0f;
        }
    }
}

// ---------------- launch ----------------
extern "C" void kernel_launch(void* const* d_in, const int* in_sizes, int n_in,
                              void* d_out, int out_size) {
    const float* q     = (const float*)d_in[0];
    const float* k     = (const float*)d_in[1];
    // d_in[2] = attention_mask (reconstructed analytically; exp(-1e9 shift) == 0 in fp32)
    const float* cos_q = (const float*)d_in[3];
    const float* sin_q = (const float*)d_in[4];
    const float* cos_k = (const float*)d_in[5];
    const float* sin_k = (const float*)d_in[6];
    const float* wq    = (const float*)d_in[7];
    const float* wk    = (const float*)d_in[8];
    float* out = (float*)d_out;

    prep_all<<<2560, 256>>>(wq, k, cos_k, sin_k, wk);

    cudaFuncSetAttribute(fused_attn, cudaFuncAttributeMaxDynamicSharedMemorySize, SMEM_TOTAL);
    fused_attn<<<dim3(Sq / MR, HKn, Bsz), NT, SMEM_TOTAL>>>(q, cos_q, sin_q, out);
}

// round 17
// speedup vs baseline: 1.1214x; 1.1214x over previous
#include <cuda_runtime.h>
#include <cuda_fp16.h>
#include <cstdint>

// Problem constants
#define Bsz 2
#define Sq 8192
#define HQ 32
#define HKn 8
#define Dd 128
#define GHd 128
#define NBl 128
#define Gg 4
#define K1 512   // G*D

#define NT 256   // threads per CTA (8 warps); 2 CTAs co-resident per SM
#define MR 64    // M rows per CTA

// ---------------- device scratch (no allocs allowed) ----------------
__device__ __align__(16) __half g_wqT_hi[HKn * GHd * K1];   // [kh][n][k]
__device__ __align__(16) __half g_wqT_lo[HKn * GHd * K1];
__device__ __align__(16) __half g_kp_hi[Bsz * HKn * NBl * GHd]; // [b][kh][n][gh]
__device__ __align__(16) __half g_kp_lo[Bsz * HKn * NBl * GHd];

// ---------------- helpers ----------------
__device__ __forceinline__ void mma16816(float* c, const uint32_t* a, const uint32_t* b) {
    asm volatile(
        "mma.sync.aligned.m16n8k16.row.col.f32.f16.f16.f32 "
        "{%0,%1,%2,%3},{%4,%5,%6,%7},{%8,%9},{%0,%1,%2,%3};\n"
        : "+f"(c[0]), "+f"(c[1]), "+f"(c[2]), "+f"(c[3])
        : "r"(a[0]), "r"(a[1]), "r"(a[2]), "r"(a[3]), "r"(b[0]), "r"(b[1]));
}

__device__ __forceinline__ void ldsm4(uint32_t* r, uint32_t addr) {
    asm volatile("ldmatrix.sync.aligned.m8n8.x4.shared.b16 {%0,%1,%2,%3},[%4];"
                 : "=r"(r[0]), "=r"(r[1]), "=r"(r[2]), "=r"(r[3]) : "r"(addr));
}

__device__ __forceinline__ void cp16(uint32_t dst, const void* src) {
    asm volatile("cp.async.cg.shared.global [%0], [%1], 16;" :: "r"(dst), "l"(src));
}
__device__ __forceinline__ void cp_commit() { asm volatile("cp.async.commit_group;" ::: "memory"); }
__device__ __forceinline__ void cp_wait_all() { asm volatile("cp.async.wait_group 0;" ::: "memory"); }

__device__ __forceinline__ uint32_t h2u(__half2 h) { return *(uint32_t*)&h; }

__device__ __forceinline__ void split_f32(float v, __half& hi, __half& lo) {
    hi = __float2half_rn(v);
    lo = __float2half_rn(v - __half2float(hi));
}

// ---------------- merged prep kernel: wq split/transpose + K path ----------------
__global__ void prep_all(const float* __restrict__ wq, const float* __restrict__ k,
                         const float* __restrict__ cosk, const float* __restrict__ sink,
                         const float* __restrict__ wk) {
    __shared__ float tile[32][33];
    __shared__ float s_a[2][Dd];
    __shared__ float s_b[2][Dd];
    __shared__ float kc[2 * Dd];
    __shared__ float kps[GHd];

    if (blockIdx.x < 512) {
        int bx = blockIdx.x;
        int kx = bx & 15;
        int ny = (bx >> 4) & 3;
        int kh = bx >> 6;
        int k0 = kx * 32;
        int n0 = ny * 32;
        int tx = threadIdx.x & 31;
        int ty4 = threadIdx.x >> 5;
        const float* src = wq + ((size_t)kh * K1 + k0) * GHd + n0;
#pragma unroll
        for (int j = 0; j < 4; j++) {
            int kk = ty4 * 4 + j;
            tile[kk][tx] = src[(size_t)kk * GHd + tx];
        }
        __syncthreads();
#pragma unroll
        for (int j = 0; j < 4; j++) {
            int nn = ty4 * 4 + j;
            float v = tile[tx][nn];
            __half hi, lo;
            split_f32(v, hi, lo);
            size_t o = ((size_t)kh * GHd + n0 + nn) * K1 + k0 + tx;
            g_wqT_hi[o] = hi;
            g_wqT_lo[o] = lo;
        }
    } else {
        int id   = blockIdx.x - 512;
        int d    = threadIdx.x & 127;
        int half = threadIdx.x >> 7;
        int n    = id & 127;
        int h    = (id >> 7) & 7;
        int b    = id >> 10;

        const float* kbase = k + (((size_t)b * Sq + (size_t)n * 64 + half * 32) * HKn + h) * Dd + d;
        float sum = 0.f;
        float mx = -3.4e38f;
#pragma unroll 8
        for (int t = 0; t < 32; t++) {
            float v = kbase[(size_t)t * (HKn * Dd)];
            sum += v;
            mx = fmaxf(mx, v);
        }
        s_a[half][d] = sum;
        s_b[half][d] = mx;
        __syncthreads();

        {
            int tt = threadIdx.x;
            kc[tt] = (tt < Dd) ? (s_a[0][tt] + s_a[1][tt]) * (1.0f / 64.0f)
                               : fmaxf(s_b[0][tt - Dd], s_b[1][tt - Dd]);
        }
        __syncthreads();

        float acc = 0.f;
        const float* wkb = wk + (size_t)h * (2 * Dd) * GHd + (size_t)(half * Dd) * GHd + d;
#pragma unroll 8
        for (int i = 0; i < Dd; i++) acc += kc[half * Dd + i] * wkb[(size_t)i * GHd];
        s_a[half][d] = acc;
        __syncthreads();

        if (half == 0) {
            kps[d] = s_a[0][d] + s_a[1][d];
        }
        __syncthreads();
        if (half == 0) {
            float full = kps[d];
            float rot = (d < 64) ? -kps[d + 64] : kps[d - 64];
            size_t ci = ((size_t)b * NBl + n) * GHd + d;
            float o = full * cosk[ci] + rot * sink[ci];
            __half hi, lo;
            split_f32(o, hi, lo);
            size_t oi = (((size_t)b * HKn + h) * NBl + n) * GHd + d;
            g_kp_hi[oi] = hi;
            g_kp_lo[oi] = lo;
        }
    }
}

// ---------------- fused kernel smem geometry (64-row CTA, 2-term phase 1) ----------------
#define LDA 72      // halves per smem row (phase1): 144B = 9*16B
#define LDQ 129     // floats (logits staging)
#define LD2 136     // halves (phase2/3 tiles): 272B
#define A_SZ 9216            // 64*LDA*2 (A hi only)
#define W_SZ 18432           // 128*LDA*2
#define BUFB 46080           // Ah(9216) Wh(18432) Wl(18432)
#define AS2_HALF 17408       // 64*LD2*2
#define AS2_OFF 0            // overlays phase-1 buffer 0
#define BS2_OFF 34816        // kp tiles (loaded after phase 1)
#define BS2_HALF 34816       // 128*LD2*2
#define SMEM_TOTAL 104448    // 2 CTAs/SM -> 208896 B

// Phase-1 warp-tile GEMM, 2-term split (q_hi*W_hi + q_hi*W_lo; q_lo term dropped).
// 8 warps, warp owns 32(m) x 32(n), n-rows {wn*16..+15} U {64+wn*16..+15}.
template <int LD, int KS>
__device__ __forceinline__ void gemm_tile2(uint32_t Ah, uint32_t Bh, uint32_t Bl,
                                           float acc[2][4][4]) {
#pragma unroll
    for (int kk = 0; kk < KS; kk++) {
        const int ks = kk * 16;
        uint32_t ah[2][4], bh[4][2], bl[4][2];
#pragma unroll
        for (int mi = 0; mi < 2; mi++)
            ldsm4(ah[mi], Ah + (mi * 16 * LD + ks) * 2);
#pragma unroll
        for (int p = 0; p < 2; p++) {
            const int prow = p * 64;
            uint32_t r[4];
            ldsm4(r, Bh + (prow * LD + ks) * 2);
            bh[2 * p][0] = r[0]; bh[2 * p][1] = r[1];
            bh[2 * p + 1][0] = r[2]; bh[2 * p + 1][1] = r[3];
            ldsm4(r, Bl + (prow * LD + ks) * 2);
            bl[2 * p][0] = r[0]; bl[2 * p][1] = r[1];
            bl[2 * p + 1][0] = r[2]; bl[2 * p + 1][1] = r[3];
        }
#pragma unroll
        for (int mi = 0; mi < 2; mi++)
#pragma unroll
            for (int nj = 0; nj < 4; nj++)
                mma16816(acc[mi][nj], ah[mi], bh[nj]);
#pragma unroll
        for (int mi = 0; mi < 2; mi++)
#pragma unroll
            for (int nj = 0; nj < 4; nj++)
                mma16816(acc[mi][nj], ah[mi], bl[nj]);
    }
}

// Phase-3 GEMM (3-term) with causal-mask group skipping.
template <int LD, int KS>
__device__ __forceinline__ void gemm_tile_attn(uint32_t Ah, uint32_t Al, uint32_t Bh, uint32_t Bl,
                                               float acc[2][4][4], bool needLo, bool needHi) {
    if (!(needLo || needHi)) return;
#pragma unroll
    for (int kk = 0; kk < KS; kk++) {
        const int ks = kk * 16;
        uint32_t ah[2][4], al[2][4], bh[4][2], bl[4][2];
#pragma unroll
        for (int mi = 0; mi < 2; mi++) {
            ldsm4(ah[mi], Ah + (mi * 16 * LD + ks) * 2);
            ldsm4(al[mi], Al + (mi * 16 * LD + ks) * 2);
        }
        if (needLo) {
            uint32_t r[4];
            ldsm4(r, Bh + ks * 2);
            bh[0][0] = r[0]; bh[0][1] = r[1]; bh[1][0] = r[2]; bh[1][1] = r[3];
            ldsm4(r, Bl + ks * 2);
            bl[0][0] = r[0]; bl[0][1] = r[1]; bl[1][0] = r[2]; bl[1][1] = r[3];
        }
        if (needHi) {
            uint32_t r[4];
            ldsm4(r, Bh + (64 * LD + ks) * 2);
            bh[2][0] = r[0]; bh[2][1] = r[1]; bh[3][0] = r[2]; bh[3][1] = r[3];
            ldsm4(r, Bl + (64 * LD + ks) * 2);
            bl[2][0] = r[0]; bl[2][1] = r[1]; bl[3][0] = r[2]; bl[3][1] = r[3];
        }
        if (needLo) {
#pragma unroll
            for (int mi = 0; mi < 2; mi++)
#pragma unroll
                for (int nj = 0; nj < 2; nj++) {
                    mma16816(acc[mi][nj], ah[mi], bh[nj]);
                    mma16816(acc[mi][nj], ah[mi], bl[nj]);
                    mma16816(acc[mi][nj], al[mi], bh[nj]);
                }
        }
        if (needHi) {
#pragma unroll
            for (int mi = 0; mi < 2; mi++)
#pragma unroll
                for (int nj = 2; nj < 4; nj++) {
                    mma16816(acc[mi][nj], ah[mi], bh[nj]);
                    mma16816(acc[mi][nj], ah[mi], bl[nj]);
                    mma16816(acc[mi][nj], al[mi], bh[nj]);
                }
        }
    }
}

__global__ void __launch_bounds__(NT, 2)
fused_attn(const float* __restrict__ q, const float* __restrict__ cosq,
           const float* __restrict__ sinq, float* __restrict__ out) {
    extern __shared__ char sm[];
    const uint32_t su = (uint32_t)__cvta_generic_to_shared(sm);

    const int t    = threadIdx.x;
    const int lane = t & 31;
    const int w    = t >> 5;       // 0..7
    const int wm   = w >> 2;       // 0..1
    const int wn   = w & 3;        // 0..3
    const int gid  = lane >> 2;
    const int tig  = lane & 3;

    // reversed s-tile mapping: last-launched CTAs get the cheapest (low-nv) tiles
    const int rbx = 127 - (int)blockIdx.x;
    const int s0 = rbx * MR;
    const int kh = blockIdx.y;
    const int b  = blockIdx.z;

    // causal block mask: valid columns for this CTA = 0 .. nv-1
    const int nv = rbx + 1;
    const bool needLo = nv > wn * 16;
    const bool needHi = nv > 64 + wn * 16;

    // ldmatrix lane offsets (bytes)
    const uint32_t aoff1 = (uint32_t)(((wm * 32 + (lane & 15)) * LDA + ((lane >> 4) << 3)) * 2);
    const uint32_t boff1 = (uint32_t)(((wn * 16 + (lane & 7) + ((lane >> 4) << 3)) * LDA +
                                       (((lane >> 3) & 1) << 3)) * 2);
    const uint32_t aoff2 = (uint32_t)(((wm * 32 + (lane & 15)) * LD2 + ((lane >> 4) << 3)) * 2);
    const uint32_t boff2 = (uint32_t)(((wn * 16 + (lane & 7) + ((lane >> 4) << 3)) * LD2 +
                                       (((lane >> 3) & 1) << 3)) * 2);

    float acc[2][4][4];
#pragma unroll
    for (int mi = 0; mi < 2; mi++)
#pragma unroll
        for (int nj = 0; nj < 4; nj++)
#pragma unroll
            for (int c = 0; c < 4; c++) acc[mi][nj][c] = 0.f;

    const float* qbase = q + ((size_t)b * Sq + s0) * (HQ * Dd) + (size_t)kh * (Gg * Dd);
    const __half* wqh = g_wqT_hi + (size_t)kh * GHd * K1;
    const __half* wql = g_wqT_lo + (size_t)kh * GHd * K1;

    // per-thread load indices (phase 1, 64-wide chunks, 256 threads)
    int qrow[4], wrow[4];
#pragma unroll
    for (int i = 0; i < 4; i++) qrow[i] = (t + NT * i) >> 4;   // 16 float4 per A row (64 rows)
    const int qc4 = (t & 15) << 2;
#pragma unroll
    for (int i = 0; i < 4; i++) wrow[i] = (t + NT * i) >> 3;   // 8 cp16 per W row (128 rows)
    const int wc8 = (t & 7) << 3;

    float4 qv[4];

    // ---- prologue: chunk 0 (weights cp.async FIRST, then the q LDG chain) ----
#pragma unroll
    for (int i = 0; i < 4; i++) {
        uint32_t d = su + A_SZ + (uint32_t)((wrow[i] * LDA + wc8) * 2);
        cp16(d, wqh + (size_t)wrow[i] * K1 + wc8);
        cp16(d + W_SZ, wql + (size_t)wrow[i] * K1 + wc8);
    }
    cp_commit();
#pragma unroll
    for (int i = 0; i < 4; i++)
        qv[i] = *(const float4*)(qbase + (size_t)qrow[i] * (HQ * Dd) + qc4);
    {
        __half* Ah = (__half*)sm;
#pragma unroll
        for (int i = 0; i < 4; i++) {
            __half2 h01 = __floats2half2_rn(qv[i].x, qv[i].y);
            __half2 h23 = __floats2half2_rn(qv[i].z, qv[i].w);
            *(uint2*)(Ah + qrow[i] * LDA + qc4) = make_uint2(h2u(h01), h2u(h23));
        }
    }

    // ===== Phase 1: Q projection (2-term), K=512 in 8 chunks of 64, double-buffered =====
    for (int c = 0; c < 8; c++) {
        cp_wait_all();
        __syncthreads();
        const int kc_next = (c + 1) * 64;
        if (c < 7) {
            uint32_t nb = su + ((c + 1) & 1) * BUFB;
#pragma unroll
            for (int i = 0; i < 4; i++) {
                uint32_t d = nb + A_SZ + (uint32_t)((wrow[i] * LDA + wc8) * 2);
                cp16(d, wqh + (size_t)wrow[i] * K1 + kc_next + wc8);
                cp16(d + W_SZ, wql + (size_t)wrow[i] * K1 + kc_next + wc8);
            }
            cp_commit();
#pragma unroll
            for (int i = 0; i < 4; i++)
                qv[i] = *(const float4*)(qbase + (size_t)qrow[i] * (HQ * Dd) + kc_next + qc4);
        }
        {
            const uint32_t bb = su + (c & 1) * BUFB;
            gemm_tile2<LDA, 4>(bb + aoff1, bb + A_SZ + boff1, bb + A_SZ + W_SZ + boff1, acc);
        }
        if (c < 7) {
            __half* Ah = (__half*)(sm + ((c + 1) & 1) * BUFB);
#pragma unroll
            for (int i = 0; i < 4; i++) {
                __half2 h01 = __floats2half2_rn(qv[i].x, qv[i].y);
                __half2 h23 = __floats2half2_rn(qv[i].z, qv[i].w);
                *(uint2*)(Ah + qrow[i] * LDA + qc4) = make_uint2(h2u(h01), h2u(h23));
            }
        }
    }
    __syncthreads();   // phase-1 buffers dead

    // ===== issue kp tile loads, only rows < nv (rounded to ldmatrix group) =====
    {
        const int nvp = (nv + 15) & ~15;
        const __half* kph = g_kp_hi + ((size_t)b * HKn + kh) * NBl * GHd;
        const __half* kpl = g_kp_lo + ((size_t)b * HKn + kh) * NBl * GHd;
#pragma unroll
        for (int i = 0; i < 8; i++) {
            int id = t + NT * i;
            int n  = id >> 4;
            int c8 = (id & 15) << 3;
            if (n < nvp) {
                uint32_t d = su + BS2_OFF + (uint32_t)((n * LD2 + c8) * 2);
                cp16(d, kph + (size_t)n * GHd + c8);
                cp16(d + BS2_HALF, kpl + (size_t)n * GHd + c8);
            }
        }
        cp_commit();
    }

    // ===== Phase 2: register RoPE + split -> As2 (hi/lo, 3-term attn) =====
    {
        __half* As2_hi = (__half*)(sm + AS2_OFF);
        __half* As2_lo = (__half*)(sm + AS2_OFF + AS2_HALF);
        const size_t rowbase = (size_t)b * Sq + s0;
#pragma unroll
        for (int j = 0; j < 2; j++) {
            const int cl = wn * 16 + j * 8 + tig * 2;
            const int ch = cl + 64;
#pragma unroll
            for (int mi = 0; mi < 2; mi++)
#pragma unroll
                for (int h = 0; h < 2; h++) {
                    int row = wm * 32 + mi * 16 + h * 8 + gid;
                    const float* crow = cosq + (rowbase + row) * GHd;
                    const float* srow = sinq + (rowbase + row) * GHd;
                    float2 c_l = *(const float2*)(crow + cl);
                    float2 c_h = *(const float2*)(crow + ch);
                    float2 s_l = *(const float2*)(srow + cl);
                    float2 s_h = *(const float2*)(srow + ch);
                    float vl0 = acc[mi][j][2 * h],     vl1 = acc[mi][j][2 * h + 1];
                    float vh0 = acc[mi][j + 2][2 * h], vh1 = acc[mi][j + 2][2 * h + 1];
                    float ol0 = vl0 * c_l.x - vh0 * s_l.x;
                    float ol1 = vl1 * c_l.y - vh1 * s_l.y;
                    float oh0 = vh0 * c_h.x + vl0 * s_h.x;
                    float oh1 = vh1 * c_h.y + vl1 * s_h.y;
                    __half2 hl = __floats2half2_rn(ol0, ol1);
                    __half2 hh = __floats2half2_rn(oh0, oh1);
                    __half2 ll = __floats2half2_rn(ol0 - __low2float(hl), ol1 - __high2float(hl));
                    __half2 lh = __floats2half2_rn(oh0 - __low2float(hh), oh1 - __high2float(hh));
                    *(uint32_t*)(As2_hi + row * LD2 + cl) = h2u(hl);
                    *(uint32_t*)(As2_hi + row * LD2 + ch) = h2u(hh);
                    *(uint32_t*)(As2_lo + row * LD2 + cl) = h2u(ll);
                    *(uint32_t*)(As2_lo + row * LD2 + ch) = h2u(lh);
                }
        }
    }
    cp_wait_all();
    __syncthreads();   // As2 + Bs2 ready

    // ===== Phase 3: attn split-GEMM K=128 (3-term), masked n-groups skipped =====
#pragma unroll
    for (int mi = 0; mi < 2; mi++)
#pragma unroll
        for (int nj = 0; nj < 4; nj++)
#pragma unroll
            for (int c = 0; c < 4; c++) acc[mi][nj][c] = 0.f;

    gemm_tile_attn<LD2, 8>(su + AS2_OFF + aoff2, su + AS2_OFF + AS2_HALF + aoff2,
                           su + BS2_OFF + boff2, su + BS2_OFF + BS2_HALF + boff2,
                           acc, needLo, needHi);
    __syncthreads();   // As2 dead

    // ===== Phase 4: logits (remapped cols), masked softmax, store =====
    float* logits = (float*)sm;
    const float scale = 0.08838834764831845f;  // 1/sqrt(128)
#pragma unroll
    for (int mi = 0; mi < 2; mi++)
#pragma unroll
        for (int nj = 0; nj < 4; nj++) {
            const bool need = (nj < 2) ? needLo : needHi;
            if (need) {
                int r = wm * 32 + mi * 16 + gid;
                int col = wn * 16 + (nj & 1) * 8 + ((nj >> 1) << 6) + tig * 2;
                logits[r * LDQ + col]           = acc[mi][nj][0] * scale;
                logits[r * LDQ + col + 1]       = acc[mi][nj][1] * scale;
                logits[(r + 8) * LDQ + col]     = acc[mi][nj][2] * scale;
                logits[(r + 8) * LDQ + col + 1] = acc[mi][nj][3] * scale;
            }
        }
    __syncthreads();

    for (int rr = 0; rr < 8; rr++) {
        int row    = w * 8 + rr;
        int sabs   = s0 + row;
        int nvalid = (sabs >> 6) + 1;
        float v[4];
#pragma unroll
        for (int j = 0; j < 4; j++) {
            int c = lane + j * 32;
            v[j] = (c < nvalid) ? logits[row * LDQ + c] : -1e30f;
        }
        float m = fmaxf(fmaxf(v[0], v[1]), fmaxf(v[2], v[3]));
#pragma unroll
        for (int o = 16; o; o >>= 1) m = fmaxf(m, __shfl_xor_sync(0xffffffffu, m, o));
        float e[4];
        float se = 0.f;
#pragma unroll
        for (int j = 0; j < 4; j++) { e[j] = __expf(v[j] - m); se += e[j]; }
#pragma unroll
        for (int o = 16; o; o >>= 1) se += __shfl_xor_sync(0xffffffffu, se, o);
        float inv = 1.0f / se;
        float* orow = out + (((size_t)b * HKn + kh) * Sq + sabs) * NBl;
#pragma unroll
        for (int j = 0; j < 4; j++) {
            int c = lane + j * 32;
            orow[c] = (c < nvalid) ? e[j] * inv : 0.0f;
        }
    }
}

// ---------------- launch ----------------
extern "C" void kernel_launch(void* const* d_in, const int* in_sizes, int n_in,
                              void* d_out, int out_size) {
    const float* q     = (const float*)d_in[0];
    const float* k     = (const float*)d_in[1];
    // d_in[2] = attention_mask (reconstructed analytically; exp(-1e9 shift) == 0 in fp32)
    const float* cos_q = (const float*)d_in[3];
    const float* sin_q = (const float*)d_in[4];
    const float* cos_k = (const float*)d_in[5];
    const float* sin_k = (const float*)d_in[6];
    const float* wq    = (const float*)d_in[7];
    const float* wk    = (const float*)d_in[8];
    float* out = (float*)d_out;

    prep_all<<<2560, 256>>>(wq, k, cos_k, sin_k, wk);

    cudaFuncSetAttribute(fused_attn, cudaFuncAttributeMaxDynamicSharedMemorySize, SMEM_TOTAL);
    fused_attn<<<dim3(Sq / MR, HKn, Bsz), NT, SMEM_TOTAL>>>(q, cos_q, sin_q, out);
}